// round 4
// baseline (speedup 1.0000x reference)
#include <cuda_runtime.h>
#include <cuda_bf16.h>
#include <cstdint>

#define NUM_DST   10000
#define NUM_EDGES 600000
#define DN   100
#define DE   172
#define DTF  100
#define DOUT 128
#define KDIM (DN + DE + DTF)   // 372
#define NKC  12                // k-chunks of 32
#define ET2  128               // edges per tile
#define NTILES ((NUM_EDGES + ET2 - 1) / ET2)   // 4688
#define FGRID  296
#define BSTRIDE 196            // B row stride in b32 units (392 bf16)
#define ASTRIDE 20             // A row stride in b32 units (40 bf16)

// smem layout (bytes)
#define SM_B   (128 * BSTRIDE * 4)          // 100352
#define SM_A   (128 * ASTRIDE * 4)          // 10240
#define SM_E   (128 * 2 * 4)                // 1024
#define SM_DST (128 * 4)
#define SM_DT  (128 * 4)
#define SM_TW  (DTF * 4)
#define SM_TB  (DTF * 4)
#define FUSED_SMEM (SM_B + SM_A + SM_E + SM_DST + SM_DT + SM_TW + SM_TB)

// ---------------- scratch ----------------------------------------------------
__device__ float g_qnodes[NUM_DST * DOUT];
__device__ float g_qbk[NUM_DST * 2];
__device__ float g_Pq[(size_t)NUM_DST * KDIM * 2];
__device__ float g_z[NUM_DST * 2];
__device__ float g_agg[NUM_DST * DOUT];
__device__ float g_qbias[DOUT];
__device__ float g_absum[2];

__device__ __forceinline__ uint32_t pack_bf16(float lo, float hi) {
    uint32_t r;
    asm("cvt.rn.bf16x2.f32 %0, %1, %2;" : "=r"(r) : "f"(hi), "f"(lo));
    return r;
}

// ---------------- kernel 0: init + derived constants -------------------------
__global__ void init_kernel(const float* __restrict__ time_b,
                            const float* __restrict__ wq,
                            const float* __restrict__ bq,
                            const float* __restrict__ att_bias)
{
    int idx = blockIdx.x * blockDim.x + threadIdx.x;
    if (idx < NUM_DST * DOUT) g_agg[idx] = 0.f;
    if (idx < NUM_DST * 2) g_z[idx] = 0.f;
    if (idx < DOUT) {
        float acc = bq[idx];
        #pragma unroll 4
        for (int t = 0; t < DTF; t++)
            acc += cosf(time_b[t]) * wq[(DN + t) * DOUT + idx];
        g_qbias[idx] = acc;
    }
    if (idx < 2) {
        float s = 0.f;
        for (int j = 0; j < DOUT / 2; j++) s += att_bias[idx * (DOUT / 2) + j];
        g_absum[idx] = s;
    }
}

// ---------------- kernel 1: Q per dst node (4 dst / block) + Q.bk ------------
__global__ __launch_bounds__(128) void qnode_kernel(const float* __restrict__ h,
                                                    const float* __restrict__ wq,
                                                    const float* __restrict__ bk)
{
    int dbase = blockIdx.x * 4;
    int c = threadIdx.x;
    __shared__ float sh[4][DN];
    __shared__ float part[4][4];
    for (int i = c; i < 4 * DN; i += 128) {
        int dl = i / DN, k = i - dl * DN;
        sh[dl][k] = h[(size_t)(dbase + dl) * DN + k];
    }
    __syncthreads();
    float qb = g_qbias[c];
    float a[4] = {qb, qb, qb, qb};
    #pragma unroll 4
    for (int k = 0; k < DN; k++) {
        float w = wq[k * DOUT + c];
        #pragma unroll
        for (int d = 0; d < 4; d++) a[d] = fmaf(sh[d][k], w, a[d]);
    }
    #pragma unroll
    for (int d = 0; d < 4; d++)
        g_qnodes[(dbase + d) * DOUT + c] = a[d];

    float bkc = bk[c];
    float p[4];
    #pragma unroll
    for (int d = 0; d < 4; d++) p[d] = a[d] * bkc;
    #pragma unroll
    for (int off = 16; off > 0; off >>= 1)
        #pragma unroll
        for (int d = 0; d < 4; d++)
            p[d] += __shfl_xor_sync(0xffffffffu, p[d], off);
    int warp = c >> 5;
    if ((c & 31) == 0)
        #pragma unroll
        for (int d = 0; d < 4; d++) part[d][warp] = p[d];
    __syncthreads();
    if (c < 8) {
        int d = c >> 1, hh = c & 1;
        g_qbk[(dbase + d) * 2 + hh] = part[d][hh * 2] + part[d][hh * 2 + 1];
    }
}

// ---------------- kernel 1b: Pq[d,k,h] = sum_c qn[d,64h+c] * wk[k,64h+c] -----
__global__ __launch_bounds__(256) void pq_kernel(const float* __restrict__ wk)
{
    __shared__ float qs[64][129];
    __shared__ float ws[64][129];
    int dbase = blockIdx.x * 64;
    int kbase = blockIdx.y * 64;
    int tid = threadIdx.x;
    for (int i = tid; i < 64 * 128; i += 256) {
        int r = i >> 7, c = i & 127;
        int d = dbase + r;
        qs[r][c] = (d < NUM_DST) ? g_qnodes[d * DOUT + c] : 0.f;
        int k = kbase + r;
        ws[r][c] = (k < KDIM) ? wk[k * DOUT + c] : 0.f;
    }
    __syncthreads();
    int tx = tid & 15, ty = tid >> 4;
    float acc[2][4][4];
    #pragma unroll
    for (int hh = 0; hh < 2; hh++)
        #pragma unroll
        for (int i = 0; i < 4; i++)
            #pragma unroll
            for (int j = 0; j < 4; j++) acc[hh][i][j] = 0.f;

    #pragma unroll 1
    for (int hh = 0; hh < 2; hh++) {
        for (int c = 0; c < 64; c++) {
            float q[4], w[4];
            #pragma unroll
            for (int i = 0; i < 4; i++) q[i] = qs[ty * 4 + i][hh * 64 + c];
            #pragma unroll
            for (int j = 0; j < 4; j++) w[j] = ws[tx * 4 + j][hh * 64 + c];
            #pragma unroll
            for (int i = 0; i < 4; i++)
                #pragma unroll
                for (int j = 0; j < 4; j++)
                    acc[hh][i][j] = fmaf(q[i], w[j], acc[hh][i][j]);
        }
    }
    #pragma unroll
    for (int i = 0; i < 4; i++) {
        int d = dbase + ty * 4 + i;
        if (d >= NUM_DST) continue;
        #pragma unroll
        for (int j = 0; j < 4; j++) {
            int k = kbase + tx * 4 + j;
            if (k >= KDIM) continue;
            g_Pq[((size_t)d * KDIM + k) * 2 + 0] = acc[0][i][j];
            g_Pq[((size_t)d * KDIM + k) * 2 + 1] = acc[1][i][j];
        }
    }
}

// ---------------- fused kernel: scores + exp + z + bf16 V GEMM + agg ---------
// Persistent: FGRID blocks, 256 thr (8 warps), 2 CTAs/SM.
// B = wv bf16 [128 n][392 k] resident. Per 128-edge tile: 12 chunks of 32 k:
// build A chunk (f32 LDG -> score FMA w/ Pq -> bf16 pack -> STS), sync,
// m16n8k16 MMA, sync. Tail: reduce scores, exp, z-atomic; epilogue scales by
// unnormalized e^s and red.adds into g_agg (out_kernel divides by z).
__global__ __launch_bounds__(256, 2) void fused_kernel(
    const float* __restrict__ h,   const float* __restrict__ ef,
    const float* __restrict__ dt,  const int*   __restrict__ dst_idx,
    const float* __restrict__ time_w, const float* __restrict__ time_b,
    const float* __restrict__ wv)
{
    extern __shared__ char smem[];
    uint32_t* sB32 = (uint32_t*)smem;                       // [128][196]
    uint32_t* sA32 = (uint32_t*)(smem + SM_B);              // [128][20]
    float*    sE   = (float*)(smem + SM_B + SM_A);          // [128][2]
    int*      sDst = (int*)(smem + SM_B + SM_A + SM_E);
    float*    sDt  = (float*)(smem + SM_B + SM_A + SM_E + SM_DST);
    float*    sTw  = (float*)(smem + SM_B + SM_A + SM_E + SM_DST + SM_DT);
    float*    sTb  = sTw + DTF;

    const int tid  = threadIdx.x;
    const int lane = tid & 31;
    const int wid  = tid >> 5;
    const int wm   = wid & 3;     // 32-edge slice
    const int wn   = wid >> 2;    // 64-col slice == head

    // ---- one-time: B (wv -> bf16, [n][k]) + time arrays ----
    for (int i = tid; i < 128 * 192; i += 256) {
        int n = i & 127;
        int kp = i >> 7;          // b32 pair index, k = 2*kp
        int k = kp * 2;
        float x0 = (k     < KDIM) ? wv[k * DOUT + n]       : 0.f;
        float x1 = (k + 1 < KDIM) ? wv[(k + 1) * DOUT + n] : 0.f;
        sB32[n * BSTRIDE + kp] = pack_bf16(x0, x1);
    }
    for (int t = tid; t < DTF; t += 256) { sTw[t] = time_w[t]; sTb[t] = time_b[t]; }

    for (int tile = blockIdx.x; tile < NTILES; tile += gridDim.x) {
        const int e_base = tile * ET2;

        // per-tile edge metadata
        if (tid < ET2) {
            int e = e_base + tid;
            bool ev = (e < NUM_EDGES);
            sDst[tid] = ev ? dst_idx[e] : 0;
            sDt[tid]  = ev ? dt[e] : 0.f;
        }
        __syncthreads();

        float acc[2][8][4];
        #pragma unroll
        for (int mf = 0; mf < 2; mf++)
            #pragma unroll
            for (int nf = 0; nf < 8; nf++)
                #pragma unroll
                for (int r = 0; r < 4; r++) acc[mf][nf][r] = 0.f;
        float sp[8][2];
        #pragma unroll
        for (int r = 0; r < 8; r++) { sp[r][0] = 0.f; sp[r][1] = 0.f; }

        #pragma unroll 1
        for (int kc = 0; kc < NKC; kc++) {
            const int K0 = kc * 32;
            // ---- build A chunk + score FMAs ----
            #pragma unroll
            for (int r = 0; r < 8; r++) {
                int idx = tid + r * 256;
                int el = idx >> 4;
                int kp = idx & 15;
                int k = K0 + kp * 2;
                int e = e_base + el;
                bool ev = (e < NUM_EDGES);
                float x0 = 0.f, x1 = 0.f;
                if (ev) {
                    if (k < DN) {
                        float2 t = *(const float2*)(h + (size_t)(NUM_DST + e) * DN + k);
                        x0 = t.x; x1 = t.y;
                    } else if (k < DN + DE) {
                        float2 t = *(const float2*)(ef + (size_t)e * DE + (k - DN));
                        x0 = t.x; x1 = t.y;
                    } else if (k < KDIM) {
                        int t0 = k - DN - DE;
                        float td = sDt[el];
                        x0 = __cosf(td * sTw[t0] + sTb[t0]);
                        x1 = __cosf(td * sTw[t0 + 1] + sTb[t0 + 1]);
                    }
                }
                if (ev && k < KDIM) {
                    const float* pqp = g_Pq + ((size_t)sDst[el] * KDIM + k) * 2;
                    float2 p0 = *(const float2*)pqp;
                    float2 p1 = *(const float2*)(pqp + 2);
                    sp[r][0] += x0 * p0.x + x1 * p1.x;
                    sp[r][1] += x0 * p0.y + x1 * p1.y;
                }
                sA32[el * ASTRIDE + kp] = pack_bf16(x0, x1);
            }
            __syncthreads();

            // ---- MMA on chunk ----
            #pragma unroll
            for (int ks = 0; ks < 2; ks++) {
                int kp0 = (lane & 3) + ks * 8;
                uint32_t a[2][4];
                #pragma unroll
                for (int mf = 0; mf < 2; mf++) {
                    int rb = wm * 32 + mf * 16 + (lane >> 2);
                    a[mf][0] = sA32[rb * ASTRIDE + kp0];
                    a[mf][1] = sA32[(rb + 8) * ASTRIDE + kp0];
                    a[mf][2] = sA32[rb * ASTRIDE + kp0 + 4];
                    a[mf][3] = sA32[(rb + 8) * ASTRIDE + kp0 + 4];
                }
                #pragma unroll
                for (int nf = 0; nf < 8; nf++) {
                    int n = wn * 64 + nf * 8 + (lane >> 2);
                    uint32_t b0 = sB32[n * BSTRIDE + kc * 16 + kp0];
                    uint32_t b1 = sB32[n * BSTRIDE + kc * 16 + kp0 + 4];
                    #pragma unroll
                    for (int mf = 0; mf < 2; mf++) {
                        asm volatile(
                            "mma.sync.aligned.m16n8k16.row.col.f32.bf16.bf16.f32 "
                            "{%0,%1,%2,%3}, {%4,%5,%6,%7}, {%8,%9}, {%0,%1,%2,%3};"
                            : "+f"(acc[mf][nf][0]), "+f"(acc[mf][nf][1]),
                              "+f"(acc[mf][nf][2]), "+f"(acc[mf][nf][3])
                            : "r"(a[mf][0]), "r"(a[mf][1]), "r"(a[mf][2]), "r"(a[mf][3]),
                              "r"(b0), "r"(b1));
                    }
                }
            }
            __syncthreads();
        }

        // ---- score tail: reduce over 16 lanes, exp, z, stash e^s ----
        #pragma unroll
        for (int r = 0; r < 8; r++) {
            float v0 = sp[r][0], v1 = sp[r][1];
            #pragma unroll
            for (int off = 8; off > 0; off >>= 1) {
                v0 += __shfl_xor_sync(0xffffffffu, v0, off);
                v1 += __shfl_xor_sync(0xffffffffu, v1, off);
            }
            if ((lane & 15) == 0) {
                int el = wid * 2 + (lane >> 4) + 16 * r;
                int e = e_base + el;
                if (e < NUM_EDGES) {
                    int d = sDst[el];
                    float s0 = v0 + g_absum[0] + g_qbk[d * 2 + 0];
                    float s1 = v1 + g_absum[1] + g_qbk[d * 2 + 1];
                    s0 = s0 > 0.f ? s0 : 0.2f * s0;
                    s1 = s1 > 0.f ? s1 : 0.2f * s1;
                    float e0 = __expf(fminf(s0, 80.f));
                    float e1 = __expf(fminf(s1, 80.f));
                    sE[el * 2 + 0] = e0;
                    sE[el * 2 + 1] = e1;
                    atomicAdd(&g_z[d * 2 + 0], e0);
                    atomicAdd(&g_z[d * 2 + 1], e1);
                }
            }
        }
        __syncthreads();

        // ---- epilogue: agg += e^s * V (unnormalized) ----
        #pragma unroll
        for (int mf = 0; mf < 2; mf++) {
            #pragma unroll
            for (int rs = 0; rs < 2; rs++) {
                int el = wm * 32 + mf * 16 + rs * 8 + (lane >> 2);
                int e = e_base + el;
                if (e >= NUM_EDGES) continue;
                int d = sDst[el];
                float es = sE[el * 2 + wn];
                #pragma unroll
                for (int nf = 0; nf < 8; nf++) {
                    int col = wn * 64 + nf * 8 + 2 * (lane & 3);
                    float vx = acc[mf][nf][rs * 2 + 0] * es;
                    float vy = acc[mf][nf][rs * 2 + 1] * es;
                    float* ptr = &g_agg[d * DOUT + col];
                    asm volatile("red.global.add.v2.f32 [%0], {%1,%2};"
                                 :: "l"(ptr), "f"(vx), "f"(vy) : "memory");
                }
            }
        }
        __syncthreads();   // protect sDst/sDt/sE before next tile overwrites
    }
}

// ---------------- output GEMM + relu + layernorm (4 dst/block) ---------------
__global__ __launch_bounds__(128) void out_kernel(
    const float* __restrict__ h,    const float* __restrict__ wout,
    const float* __restrict__ bout, const float* __restrict__ bv,
    const float* __restrict__ ln_g, const float* __restrict__ ln_b,
    float* __restrict__ out)
{
    int dbase = blockIdx.x * 4;
    int c = threadIdx.x;
    __shared__ float sin[4][DOUT + DN];
    __shared__ float red1[4][4], red2[4][4];
    for (int i = c; i < 4 * (DOUT + DN); i += 128) {
        int dl = i / (DOUT + DN), k = i - dl * (DOUT + DN);
        int d = dbase + dl;
        float v;
        if (k < DOUT) {
            float zk = g_z[d * 2 + (k >> 6)];
            float av = g_agg[d * DOUT + k];
            v = (zk > 0.f) ? (av / zk + bv[k]) : 0.f;
        } else {
            v = h[(size_t)d * DN + (k - DOUT)];
        }
        sin[dl][k] = v;
    }
    __syncthreads();

    float b0 = bout[c];
    float a[4] = {b0, b0, b0, b0};
    #pragma unroll 4
    for (int k = 0; k < DOUT + DN; k++) {
        float w = wout[k * DOUT + c];
        #pragma unroll
        for (int d = 0; d < 4; d++) a[d] = fmaf(sin[d][k], w, a[d]);
    }
    float s1[4], s2[4];
    #pragma unroll
    for (int d = 0; d < 4; d++) {
        a[d] = fmaxf(a[d], 0.f);
        s1[d] = a[d];
        s2[d] = a[d] * a[d];
    }
    #pragma unroll
    for (int off = 16; off > 0; off >>= 1) {
        #pragma unroll
        for (int d = 0; d < 4; d++) {
            s1[d] += __shfl_xor_sync(0xffffffffu, s1[d], off);
            s2[d] += __shfl_xor_sync(0xffffffffu, s2[d], off);
        }
    }
    int warp = c >> 5;
    if ((c & 31) == 0) {
        #pragma unroll
        for (int d = 0; d < 4; d++) { red1[d][warp] = s1[d]; red2[d][warp] = s2[d]; }
    }
    __syncthreads();
    #pragma unroll
    for (int d = 0; d < 4; d++) {
        float t1 = red1[d][0] + red1[d][1] + red1[d][2] + red1[d][3];
        float t2 = red2[d][0] + red2[d][1] + red2[d][2] + red2[d][3];
        float mu  = t1 * (1.f / DOUT);
        float var = t2 * (1.f / DOUT) - mu * mu;
        out[(size_t)(dbase + d) * DOUT + c] =
            (a[d] - mu) * rsqrtf(var + 1e-5f) * ln_g[c] + ln_b[c];
    }
}

// ---------------- launch -----------------------------------------------------
extern "C" void kernel_launch(void* const* d_in, const int* in_sizes, int n_in,
                              void* d_out, int out_size)
{
    int off = (n_in >= 18 && in_sizes[4] == 1) ? 1 : 0;
    const float* h        = (const float*)d_in[0];
    const float* ef       = (const float*)d_in[1];
    const float* dt       = (const float*)d_in[2];
    const int*   dst_idx  = (const int*)  d_in[3];
    const float* time_w   = (const float*)d_in[4 + off];
    const float* time_b   = (const float*)d_in[5 + off];
    const float* wq       = (const float*)d_in[6 + off];
    const float* bq       = (const float*)d_in[7 + off];
    const float* wk       = (const float*)d_in[8 + off];
    const float* bk       = (const float*)d_in[9 + off];
    const float* wv       = (const float*)d_in[10 + off];
    const float* bv       = (const float*)d_in[11 + off];
    const float* att_bias = (const float*)d_in[12 + off];
    const float* wout     = (const float*)d_in[13 + off];
    const float* bout     = (const float*)d_in[14 + off];
    const float* ln_g     = (const float*)d_in[15 + off];
    const float* ln_b     = (const float*)d_in[16 + off];
    float* out = (float*)d_out;

    cudaFuncSetAttribute(fused_kernel,
                         cudaFuncAttributeMaxDynamicSharedMemorySize, FUSED_SMEM);

    init_kernel<<<(NUM_DST * DOUT + 255) / 256, 256>>>(time_b, wq, bq, att_bias);
    qnode_kernel<<<NUM_DST / 4, 128>>>(h, wq, bk);
    pq_kernel<<<dim3((NUM_DST + 63) / 64, (KDIM + 63) / 64), 256>>>(wk);
    fused_kernel<<<FGRID, 256, FUSED_SMEM>>>(h, ef, dt, dst_idx,
                                             time_w, time_b, wv);
    out_kernel<<<NUM_DST / 4, 128>>>(h, wout, bout, bv, ln_g, ln_b, out);
}

// round 5
// speedup vs baseline: 2.3105x; 2.3105x over previous
#include <cuda_runtime.h>
#include <cuda_bf16.h>
#include <cstdint>

#define NUM_DST   10000
#define NUM_EDGES 600000
#define DN   100
#define DE   172
#define DTF  100
#define DOUT 128
#define KDIM (DN + DE + DTF)   // 372
#define NKC  12                // k-chunks of 32

// ---------------- scratch ----------------------------------------------------
__device__ float  g_qnodes[NUM_DST * DOUT];
__device__ float  g_qbk[NUM_DST * 2];
__device__ float  g_Pq[(size_t)NUM_DST * KDIM * 2];
__device__ float2 g_U[(size_t)NUM_DST * KDIM];        // [d][k] -> (head0, head1)
__device__ float  g_z[NUM_DST * 2];
__device__ float  g_agg[NUM_DST * DOUT];
__device__ float  g_qbias[DOUT];
__device__ float  g_absum[2];

// ---------------- kernel 0: init + derived constants -------------------------
__global__ void init_kernel(const float* __restrict__ time_b,
                            const float* __restrict__ wq,
                            const float* __restrict__ bq,
                            const float* __restrict__ att_bias)
{
    int idx = blockIdx.x * blockDim.x + threadIdx.x;
    if (idx < NUM_DST * KDIM) g_U[idx] = make_float2(0.f, 0.f);
    if (idx < NUM_DST * 2) g_z[idx] = 0.f;
    if (idx < DOUT) {
        float acc = bq[idx];
        #pragma unroll 4
        for (int t = 0; t < DTF; t++)
            acc += cosf(time_b[t]) * wq[(DN + t) * DOUT + idx];
        g_qbias[idx] = acc;
    }
    if (idx < 2) {
        float s = 0.f;
        for (int j = 0; j < DOUT / 2; j++) s += att_bias[idx * (DOUT / 2) + j];
        g_absum[idx] = s;
    }
}

// ---------------- kernel 1: Q per dst node (4 dst / block) + Q.bk ------------
__global__ __launch_bounds__(128) void qnode_kernel(const float* __restrict__ h,
                                                    const float* __restrict__ wq,
                                                    const float* __restrict__ bk)
{
    int dbase = blockIdx.x * 4;
    int c = threadIdx.x;
    __shared__ float sh[4][DN];
    __shared__ float part[4][4];
    for (int i = c; i < 4 * DN; i += 128) {
        int dl = i / DN, k = i - dl * DN;
        sh[dl][k] = h[(size_t)(dbase + dl) * DN + k];
    }
    __syncthreads();
    float qb = g_qbias[c];
    float a[4] = {qb, qb, qb, qb};
    #pragma unroll 4
    for (int k = 0; k < DN; k++) {
        float w = wq[k * DOUT + c];
        #pragma unroll
        for (int d = 0; d < 4; d++) a[d] = fmaf(sh[d][k], w, a[d]);
    }
    #pragma unroll
    for (int d = 0; d < 4; d++)
        g_qnodes[(dbase + d) * DOUT + c] = a[d];

    // qbk[d][h] = sum_c q[d][c] * bk[c]  (head h = cols 64h..64h+63)
    float bkc = bk[c];
    float p[4];
    #pragma unroll
    for (int d = 0; d < 4; d++) p[d] = a[d] * bkc;
    #pragma unroll
    for (int off = 16; off > 0; off >>= 1)
        #pragma unroll
        for (int d = 0; d < 4; d++)
            p[d] += __shfl_xor_sync(0xffffffffu, p[d], off);
    int warp = c >> 5;
    if ((c & 31) == 0)
        #pragma unroll
        for (int d = 0; d < 4; d++) part[d][warp] = p[d];
    __syncthreads();
    if (c < 8) {
        int d = c >> 1, hh = c & 1;
        g_qbk[(dbase + d) * 2 + hh] = part[d][hh * 2] + part[d][hh * 2 + 1];
    }
}

// ---------------- kernel 1b: Pq[d,k,h] = sum_c qn[d,64h+c] * wk[k,64h+c] -----
__global__ __launch_bounds__(256) void pq_kernel(const float* __restrict__ wk)
{
    __shared__ float qs[64][129];
    __shared__ float ws[64][129];
    int dbase = blockIdx.x * 64;
    int kbase = blockIdx.y * 64;
    int tid = threadIdx.x;
    for (int i = tid; i < 64 * 128; i += 256) {
        int r = i >> 7, c = i & 127;
        int d = dbase + r;
        qs[r][c] = (d < NUM_DST) ? g_qnodes[d * DOUT + c] : 0.f;
        int k = kbase + r;
        ws[r][c] = (k < KDIM) ? wk[k * DOUT + c] : 0.f;
    }
    __syncthreads();
    int tx = tid & 15, ty = tid >> 4;
    float acc[2][4][4];
    #pragma unroll
    for (int hh = 0; hh < 2; hh++)
        #pragma unroll
        for (int i = 0; i < 4; i++)
            #pragma unroll
            for (int j = 0; j < 4; j++) acc[hh][i][j] = 0.f;

    #pragma unroll 1
    for (int hh = 0; hh < 2; hh++) {
        for (int c = 0; c < 64; c++) {
            float q[4], w[4];
            #pragma unroll
            for (int i = 0; i < 4; i++) q[i] = qs[ty * 4 + i][hh * 64 + c];
            #pragma unroll
            for (int j = 0; j < 4; j++) w[j] = ws[tx * 4 + j][hh * 64 + c];
            #pragma unroll
            for (int i = 0; i < 4; i++)
                #pragma unroll
                for (int j = 0; j < 4; j++)
                    acc[hh][i][j] = fmaf(q[i], w[j], acc[hh][i][j]);
        }
    }
    #pragma unroll
    for (int i = 0; i < 4; i++) {
        int d = dbase + ty * 4 + i;
        if (d >= NUM_DST) continue;
        #pragma unroll
        for (int j = 0; j < 4; j++) {
            int k = kbase + tx * 4 + j;
            if (k >= KDIM) continue;
            g_Pq[((size_t)d * KDIM + k) * 2 + 0] = acc[0][i][j];
            g_Pq[((size_t)d * KDIM + k) * 2 + 1] = acc[1][i][j];
        }
    }
}

// ---------------- kernel 2: fused score + exp + z + U accumulation -----------
// One warp per edge. kv values stay in registers after the score dot; each
// lane then red.adds e^s-weighted kv into U[dst] (float2: both heads at once).
__global__ __launch_bounds__(256) void scoreU_kernel(
    const float* __restrict__ h,   const float* __restrict__ ef,
    const float* __restrict__ dt,  const int*   __restrict__ dst_idx,
    const float* __restrict__ time_w, const float* __restrict__ time_b)
{
    int e = (blockIdx.x * 256 + threadIdx.x) >> 5;
    if (e >= NUM_EDGES) return;
    int lane = threadIdx.x & 31;
    float td = dt[e];
    int d = dst_idx[e];
    const float* __restrict__ hrow  = h + (size_t)(NUM_DST + e) * DN;
    const float* __restrict__ efrow = ef + (size_t)e * DE;

    // prefetch all kv values (high MLP)
    float v[NKC];
    #pragma unroll
    for (int it = 0; it < NKC; it++) {
        int k = it * 32 + lane;
        float x = 0.f;
        if (k < DN)            x = hrow[k];
        else if (k < DN + DE)  x = efrow[k - DN];
        else if (k < KDIM) { int t = k - DN - DE; x = __cosf(td * time_w[t] + time_b[t]); }
        v[it] = x;
    }
    const float2* __restrict__ pq = (const float2*)(g_Pq + (size_t)d * KDIM * 2);
    float2 p[NKC];
    #pragma unroll
    for (int it = 0; it < NKC; it++) {
        int k = it * 32 + lane;
        p[it] = (k < KDIM) ? pq[k] : make_float2(0.f, 0.f);
    }
    float a0 = 0.f, a1 = 0.f;
    #pragma unroll
    for (int it = 0; it < NKC; it++) {
        a0 = fmaf(v[it], p[it].x, a0);
        a1 = fmaf(v[it], p[it].y, a1);
    }
    #pragma unroll
    for (int off = 16; off > 0; off >>= 1) {
        a0 += __shfl_xor_sync(0xffffffffu, a0, off);
        a1 += __shfl_xor_sync(0xffffffffu, a1, off);
    }
    // all lanes hold the full sums after butterfly reduce
    float s0 = a0 + g_absum[0] + g_qbk[d * 2 + 0];
    float s1 = a1 + g_absum[1] + g_qbk[d * 2 + 1];
    s0 = s0 > 0.f ? s0 : 0.2f * s0;
    s1 = s1 > 0.f ? s1 : 0.2f * s1;
    float e0 = __expf(fminf(s0, 80.f));
    float e1 = __expf(fminf(s1, 80.f));
    if (lane == 0) {
        atomicAdd(&g_z[d * 2 + 0], e0);
        atomicAdd(&g_z[d * 2 + 1], e1);
    }
    // U[d][k] += (e0*v, e1*v) — lanes hit consecutive float2s (coalesced)
    float2* __restrict__ Urow = g_U + (size_t)d * KDIM;
    #pragma unroll
    for (int it = 0; it < NKC; it++) {
        int k = it * 32 + lane;
        if (k < KDIM) {
            float ux = v[it] * e0;
            float uy = v[it] * e1;
            asm volatile("red.global.add.v2.f32 [%0], {%1,%2};"
                         :: "l"(Urow + k), "f"(ux), "f"(uy) : "memory");
        }
    }
}

// ---------------- kernel 3: agg = (U/z) @ wv + bv  (8 dst / block) -----------
__global__ __launch_bounds__(128) void aggmm_kernel(const float* __restrict__ wv,
                                                    const float* __restrict__ bv)
{
    int dbase = blockIdx.x * 8;
    int c = threadIdx.x;       // output column 0..127
    int hh = c >> 6;           // head of this column
    __shared__ float sU[8][KDIM * 2];   // [d][k*2+h], already divided by z
    __shared__ float sZ[8][2];

    if (c < 16) {
        int d = c >> 1, j = c & 1;
        sZ[d][j] = g_z[(dbase + d) * 2 + j];
    }
    __syncthreads();
    for (int i = c; i < 8 * KDIM * 2; i += 128) {
        int d = i / (KDIM * 2);
        int j = i - d * (KDIM * 2);
        float z = sZ[d][j & 1];
        float u = ((const float*)(g_U + (size_t)(dbase + d) * KDIM))[j];
        sU[d][j] = (z > 0.f) ? (u / z) : 0.f;
    }
    __syncthreads();

    float acc[8];
    #pragma unroll
    for (int d = 0; d < 8; d++) acc[d] = 0.f;
    #pragma unroll 4
    for (int k = 0; k < KDIM; k++) {
        float w = wv[k * DOUT + c];
        #pragma unroll
        for (int d = 0; d < 8; d++)
            acc[d] = fmaf(sU[d][k * 2 + hh], w, acc[d]);
    }
    float bvc = bv[c];
    #pragma unroll
    for (int d = 0; d < 8; d++) {
        float r = (sZ[d][hh] > 0.f) ? (acc[d] + bvc) : 0.f;
        g_agg[(dbase + d) * DOUT + c] = r;
    }
}

// ---------------- kernel 4: output GEMM + relu + layernorm (4 dst/block) -----
__global__ __launch_bounds__(128) void out_kernel(
    const float* __restrict__ h,    const float* __restrict__ wout,
    const float* __restrict__ bout, const float* __restrict__ ln_g,
    const float* __restrict__ ln_b, float* __restrict__ out)
{
    int dbase = blockIdx.x * 4;
    int c = threadIdx.x;
    __shared__ float sin[4][DOUT + DN];
    __shared__ float red1[4][4], red2[4][4];
    for (int i = c; i < 4 * (DOUT + DN); i += 128) {
        int dl = i / (DOUT + DN), k = i - dl * (DOUT + DN);
        int d = dbase + dl;
        float v;
        if (k < DOUT) v = g_agg[d * DOUT + k];
        else          v = h[(size_t)d * DN + (k - DOUT)];
        sin[dl][k] = v;
    }
    __syncthreads();

    float b0 = bout[c];
    float a[4] = {b0, b0, b0, b0};
    #pragma unroll 4
    for (int k = 0; k < DOUT + DN; k++) {
        float w = wout[k * DOUT + c];
        #pragma unroll
        for (int d = 0; d < 4; d++) a[d] = fmaf(sin[d][k], w, a[d]);
    }
    float s1[4], s2[4];
    #pragma unroll
    for (int d = 0; d < 4; d++) {
        a[d] = fmaxf(a[d], 0.f);
        s1[d] = a[d];
        s2[d] = a[d] * a[d];
    }
    #pragma unroll
    for (int off = 16; off > 0; off >>= 1) {
        #pragma unroll
        for (int d = 0; d < 4; d++) {
            s1[d] += __shfl_xor_sync(0xffffffffu, s1[d], off);
            s2[d] += __shfl_xor_sync(0xffffffffu, s2[d], off);
        }
    }
    int warp = c >> 5;
    if ((c & 31) == 0) {
        #pragma unroll
        for (int d = 0; d < 4; d++) { red1[d][warp] = s1[d]; red2[d][warp] = s2[d]; }
    }
    __syncthreads();
    #pragma unroll
    for (int d = 0; d < 4; d++) {
        float t1 = red1[d][0] + red1[d][1] + red1[d][2] + red1[d][3];
        float t2 = red2[d][0] + red2[d][1] + red2[d][2] + red2[d][3];
        float mu  = t1 * (1.f / DOUT);
        float var = t2 * (1.f / DOUT) - mu * mu;
        out[(size_t)(dbase + d) * DOUT + c] =
            (a[d] - mu) * rsqrtf(var + 1e-5f) * ln_g[c] + ln_b[c];
    }
}

// ---------------- launch -----------------------------------------------------
extern "C" void kernel_launch(void* const* d_in, const int* in_sizes, int n_in,
                              void* d_out, int out_size)
{
    int off = (n_in >= 18 && in_sizes[4] == 1) ? 1 : 0;
    const float* h        = (const float*)d_in[0];
    const float* ef       = (const float*)d_in[1];
    const float* dt       = (const float*)d_in[2];
    const int*   dst_idx  = (const int*)  d_in[3];
    const float* time_w   = (const float*)d_in[4 + off];
    const float* time_b   = (const float*)d_in[5 + off];
    const float* wq       = (const float*)d_in[6 + off];
    const float* bq       = (const float*)d_in[7 + off];
    const float* wk       = (const float*)d_in[8 + off];
    const float* bk       = (const float*)d_in[9 + off];
    const float* wv       = (const float*)d_in[10 + off];
    const float* bv       = (const float*)d_in[11 + off];
    const float* att_bias = (const float*)d_in[12 + off];
    const float* wout     = (const float*)d_in[13 + off];
    const float* bout     = (const float*)d_in[14 + off];
    const float* ln_g     = (const float*)d_in[15 + off];
    const float* ln_b     = (const float*)d_in[16 + off];
    float* out = (float*)d_out;

    init_kernel<<<(NUM_DST * KDIM + 255) / 256, 256>>>(time_b, wq, bq, att_bias);
    qnode_kernel<<<NUM_DST / 4, 128>>>(h, wq, bk);
    pq_kernel<<<dim3((NUM_DST + 63) / 64, (KDIM + 63) / 64), 256>>>(wk);
    scoreU_kernel<<<NUM_EDGES / 8, 256>>>(h, ef, dt, dst_idx, time_w, time_b);
    aggmm_kernel<<<NUM_DST / 8, 128>>>(wv, bv);
    out_kernel<<<NUM_DST / 4, 128>>>(h, wout, bout, ln_g, ln_b, out);
}